// round 15
// baseline (speedup 1.0000x reference)
#include <cuda_runtime.h>
#include <cuda_bf16.h>
#include <cuda_fp16.h>
#include <math.h>

#define NN 48758
#define EMAX 780000
#define NB 48    // ceil(NN/1024)
#define MT 381   // ceil(NN/128)
#define TIL0 191 // chunk0 row tiles
#define NC0 (TIL0 * 128)   // 24448 rows/nodes in chunk0

// ---------------- device scratch ----------------
__device__ __align__(16) __half g_h16[(size_t)NN * 128];       // proj output (fp16, pre-BN)
__device__ __align__(16) __half g_xs[(size_t)NN * 128];        // x as fp16 (GEMM A)
__device__ __align__(16) __half g_hs[(size_t)NN * 128];        // h post-BN/relu fp16 (GEMM A)
__device__ __align__(16) __half g_zs[(size_t)NN * 128];        // z fp16 (GEMM A)
__device__ __align__(16) float    g_xw[(size_t)NN * 128];      // fp32 xw (edge gather)
__device__ __align__(16) unsigned g_erp[(size_t)NN * 512];     // packed bf16x2 (er, p)
__device__ int   g_off[NN + 1];
__device__ int   g_cur[NN];
__device__ int   g_degsrc[NN];
__device__ int   g_degdst[NN];
__device__ float g_dinv[NN];
__device__ __align__(8) int2 g_pknrm[EMAX];                    // {pk, nrm bits}
__device__ int   g_bsum[64];
__device__ float g_colsum[128], g_colsq[128];
__device__ float g_wc1[128 * 640];
__device__ float g_bc0[640], g_bc1[640], g_b01[640];
__device__ __half g_wc0h[128 * 640], g_wc0l[128 * 640];
__device__ __half g_w01h[128 * 640], g_w01l[128 * 640];
__device__ __half g_pwh[128 * 128], g_pwl[128 * 128];
__device__ __half g_owh[128 * 128], g_owl[128 * 128];

__device__ __forceinline__ float dinvf(int dg) {
    return dg > 0 ? rsqrtf((float)dg) : 0.0f;
}

// ---------------- CSR build ----------------
__global__ void zero_kernel() {
    int i = blockIdx.x * blockDim.x + threadIdx.x;
    if (i < NN) { g_degsrc[i] = 0; g_degdst[i] = 0; }
    if (i < 128) { g_colsum[i] = 0.0f; g_colsq[i] = 0.0f; }
}

__global__ void hist_kernel(const int* __restrict__ ei, int E) {
    int e = blockIdx.x * blockDim.x + threadIdx.x;
    if (e >= E) return;
    atomicAdd(&g_degdst[ei[e]], 1);
    atomicAdd(&g_degsrc[ei[E + e]], 1);
}

// block sums of degdst + dinv table
__global__ void scan1_kernel() {
    __shared__ int sm[1024];
    int tid = threadIdx.x;
    int i = blockIdx.x * 1024 + tid;
    if (i < NN) g_dinv[i] = dinvf(g_degsrc[i]);
    int v = (i < NN) ? g_degdst[i] : 0;
    sm[tid] = v;
    __syncthreads();
    for (int ofs = 512; ofs > 0; ofs >>= 1) {
        if (tid < ofs) sm[tid] += sm[tid + ofs];
        __syncthreads();
    }
    if (tid == 0) g_bsum[blockIdx.x] = sm[0];
}

// full scan (block-local inclusive + inline scan of block sums)
__global__ void scan3_kernel(int E) {
    __shared__ int sm[1024];
    __shared__ int base_s;
    int tid = threadIdx.x;
    int i = blockIdx.x * 1024 + tid;
    int v = (i < NN) ? g_degdst[i] : 0;
    sm[tid] = v;
    if (tid == 0) {
        int b = 0;
        for (int j = 0; j < blockIdx.x; j++) b += g_bsum[j];
        base_s = b;
    }
    __syncthreads();
    for (int ofs = 1; ofs < 1024; ofs <<= 1) {
        int t = (tid >= ofs) ? sm[tid - ofs] : 0;
        __syncthreads();
        sm[tid] += t;
        __syncthreads();
    }
    if (i < NN) {
        int exv = base_s + sm[tid] - v;
        g_off[i] = exv;
        g_cur[i] = exv;
        if (i == NN - 1) g_off[NN] = E;
    }
}

__global__ void scatter_kernel(const int* __restrict__ ei, const int* __restrict__ et, int E) {
    int e = blockIdx.x * blockDim.x + threadIdx.x;
    if (e >= E) return;
    int d = ei[e];
    int s = ei[E + e];
    int slot = atomicAdd(&g_cur[d], 1);
    float nrm = g_dinv[d] * g_dinv[s];
    g_pknrm[slot] = make_int2((s << 2) | et[e], __float_as_int(nrm));
}

// ---------------- prep ----------------
__device__ __forceinline__ void split_write_h(__half* dh, __half* dl, int i, float f) {
    __half h = __float2half_rn(f);
    dh[i] = h;
    dl[i] = __float2half_rn(f - __half2float(h));
}

#define XS (NN * 128)
#define XS4 (XS / 4)
// prep1x: critical path — x conv (vectorized) + pw split (vectorized)
__global__ void prep1x_kernel(const float* __restrict__ x, const float* __restrict__ pw) {
    int i = blockIdx.x * blockDim.x + threadIdx.x;
    if (i < XS4) {
        float4 v = *(const float4*)(x + (size_t)i * 4);
        __half2 a = __floats2half2_rn(v.x, v.y);
        __half2 b = __floats2half2_rn(v.z, v.w);
        *(uint2*)(g_xs + (size_t)i * 4) = make_uint2(*(unsigned*)&a, *(unsigned*)&b);
        return;
    }
    int j = i - XS4;
    if (j < 4096) {
        float4 v = *(const float4*)(pw + j * 4);
        __half h0 = __float2half_rn(v.x), h1 = __float2half_rn(v.y);
        __half h2 = __float2half_rn(v.z), h3 = __float2half_rn(v.w);
        __half l0 = __float2half_rn(v.x - __half2float(h0));
        __half l1 = __float2half_rn(v.y - __half2float(h1));
        __half l2 = __float2half_rn(v.z - __half2float(h2));
        __half l3 = __float2half_rn(v.w - __half2float(h3));
        __half2 ph0 = __halves2half2(h0, h1), ph1 = __halves2half2(h2, h3);
        __half2 pl0 = __halves2half2(l0, l1), pl1 = __halves2half2(l2, l3);
        *(uint2*)(g_pwh + j * 4) = make_uint2(*(unsigned*)&ph0, *(unsigned*)&ph1);
        *(uint2*)(g_pwl + j * 4) = make_uint2(*(unsigned*)&pl0, *(unsigned*)&pl1);
    }
}

// prep1w: weight prep (on s3, overlapped)
__global__ void prep1w_kernel(const float* __restrict__ ow, const float* __restrict__ ww,
                              const float* __restrict__ wr, const float* __restrict__ wbv) {
    int j = blockIdx.x * blockDim.x + threadIdx.x;
    if (j < 16384) { split_write_h(g_owh, g_owl, j, ow[16384 + j]); return; }
    j -= 16384;
    if (j < 163840) {
        int l = j / 81920, rem = j % 81920, k = rem / 640, n = rem % 640;
        float v;
        if (n < 128) {
            v = ww[l * 16384 + k * 128 + n];
        } else {
            int r = (n - 128) >> 7, nn = (n - 128) & 127;
            const float* a = ww + l * 16384 + k * 128;
            const float* b = wr + (size_t)((l * 4 + r) * 128) * 128 + nn;
            float s = 0.f;
            for (int q = 0; q < 128; q++) s += a[q] * b[(size_t)q * 128];
            v = s;
        }
        if (l) g_wc1[rem] = v;
        else   split_write_h(g_wc0h, g_wc0l, rem, v);
        return;
    }
    j -= 163840;
    if (j < 1280) {
        int l = j / 640, n = j % 640;
        float v;
        if (n < 128) {
            v = wbv[l * 128 + n];
        } else {
            int r = (n - 128) >> 7, nn = (n - 128) & 127;
            const float* a = wbv + l * 128;
            const float* b = wr + (size_t)((l * 4 + r) * 128) * 128 + nn;
            float s = 0.f;
            for (int q = 0; q < 128; q++) s += a[q] * b[(size_t)q * 128];
            v = s;
        }
        (l ? g_bc1 : g_bc0)[n] = v;
    }
}

// W01 = ow0 @ wc1 (split) ; b01 = ob0 @ wc1 + bc1
__global__ void prep2_kernel(const float* __restrict__ ow, const float* __restrict__ obv) {
    int i = blockIdx.x * blockDim.x + threadIdx.x;
    if (i < 81920) {
        int k = i / 640, n = i % 640;
        const float* a = ow + k * 128;
        float s = 0.f;
        for (int q = 0; q < 128; q++) s += a[q] * g_wc1[q * 640 + n];
        split_write_h(g_w01h, g_w01l, i, s);
        return;
    }
    int n = i - 81920;
    if (n < 640) {
        float s = 0.f;
        for (int q = 0; q < 128; q++) s += obv[q] * g_wc1[q * 640 + n];
        g_b01[n] = s + g_bc1[n];
    }
}

// ---------------- tensor-core GEMM (fp16 A + split-fp16 B, cp.async) ----------------
#define LDSM_X4(R, p) asm volatile( \
    "ldmatrix.sync.aligned.m8n8.x4.shared.b16 {%0,%1,%2,%3}, [%4];" \
    : "=r"((R)[0]), "=r"((R)[1]), "=r"((R)[2]), "=r"((R)[3]) : "r"(p))
#define LDSM_X2T(R, p) asm volatile( \
    "ldmatrix.sync.aligned.m8n8.x2.trans.shared.b16 {%0,%1}, [%2];" \
    : "=r"((R)[0]), "=r"((R)[1]) : "r"(p))
#define MMA_F16(d, a, b) asm volatile( \
    "mma.sync.aligned.m16n8k16.row.col.f32.f16.f16.f32 " \
    "{%0,%1,%2,%3},{%4,%5,%6,%7},{%8,%9},{%0,%1,%2,%3};" \
    : "+f"((d)[0]), "+f"((d)[1]), "+f"((d)[2]), "+f"((d)[3]) \
    : "r"((a)[0]), "r"((a)[1]), "r"((a)[2]), "r"((a)[3]), "r"((b)[0]), "r"((b)[1]))

__device__ __forceinline__ void cpa16(void* dst, const void* src, int sz) {
    unsigned d = (unsigned)__cvta_generic_to_shared(dst);
    asm volatile("cp.async.cg.shared.global [%0], [%1], 16, %2;" :: "r"(d), "l"(src), "r"(sz));
}
__device__ __forceinline__ void cpa_commit() { asm volatile("cp.async.commit_group;"); }

__device__ __forceinline__ unsigned packerp(float v) {
    float er = __expf(v);
    float p = v * er;
    __nv_bfloat162 t = __halves2bfloat162(__float2bfloat16_rn(er), __float2bfloat16_rn(p));
    return *reinterpret_cast<unsigned*>(&t);
}

// MODE 0: g_h16 = fp16(acc + bias) + fused column stats
// MODE 1: bn==0 -> g_xw fp32 (split-B) ; bn>0 -> g_erp packerp (single-B)
// MODE 2: C = gelu(acc + bias), rows via ridx gather on A
// mt0: row-tile offset (chunked pipelining)
template <int MODE>
__global__ __launch_bounds__(256, 2)
void gemm_f16(const __half* __restrict__ A,
              const __half* __restrict__ Bh, const __half* __restrict__ Bl,
              const float* __restrict__ bias, float* __restrict__ C,
              int M, int ldb, int ldc, const int* __restrict__ ridx, int mt0) {
    __shared__ __align__(16) __half Ahs[2][128][40];
    __shared__ __align__(16) __half Bhs[2][32][136];
    __shared__ __align__(16) __half Bls[2][32][136];

    int tid = threadIdx.x, lane = tid & 31, warp = tid >> 5;
    int wm = warp >> 2, wn = warp & 3;
    int bm = (blockIdx.y + mt0) * 128, bn = blockIdx.x * 128;
    const bool use_blo = (MODE != 1) || (bn == 0);

    float acc[4][4][4];
#pragma unroll
    for (int a = 0; a < 4; a++)
#pragma unroll
        for (int b = 0; b < 4; b++)
#pragma unroll
            for (int c = 0; c < 4; c++) acc[a][b][c] = 0.0f;

    int arr[2], asz[2];
#pragma unroll
    for (int i = 0; i < 2; i++) {
        int row = (tid + i * 256) >> 2;
        int grow = bm + row;
        bool ok = grow < M;
        arr[i] = ok ? (ridx ? ridx[grow] : grow) : 0;
        asz[i] = ok ? 16 : 0;
    }

#define LOAD_CHUNK(st, k0)                                                        \
    {                                                                             \
        _Pragma("unroll")                                                         \
        for (int i = 0; i < 2; i++) {                                             \
            int vec = tid + i * 256;                                              \
            int row = vec >> 2;                                                   \
            int c8 = (vec & 3) * 8;                                               \
            size_t go = (size_t)arr[i] * 128 + (k0) + c8;                         \
            cpa16(&Ahs[st][row][c8], A + go, asz[i]);                             \
        }                                                                         \
        _Pragma("unroll")                                                         \
        for (int i = 0; i < 2; i++) {                                             \
            int vec = tid + i * 256;                                              \
            int row = vec >> 4;                                                   \
            int c8 = (vec & 15) * 8;                                              \
            size_t go = (size_t)((k0) + row) * ldb + bn + c8;                     \
            cpa16(&Bhs[st][row][c8], Bh + go, 16);                                \
            if (use_blo) cpa16(&Bls[st][row][c8], Bl + go, 16);                   \
        }                                                                         \
        cpa_commit();                                                             \
    }

    LOAD_CHUNK(0, 0)
    LOAD_CHUNK(1, 32)

#pragma unroll
    for (int k0i = 0; k0i < 4; k0i++) {
        int st = k0i & 1;
        if (k0i < 3) asm volatile("cp.async.wait_group 1;");
        else         asm volatile("cp.async.wait_group 0;");
        __syncthreads();

#pragma unroll
        for (int k16 = 0; k16 < 32; k16 += 16) {
            unsigned af[4][4], bhf[4][2], blf[4][2];
            int arow = wm * 64 + (lane & 15);
            int acol = k16 + ((lane >> 4) << 3);
#pragma unroll
            for (int mt = 0; mt < 4; mt++) {
                unsigned p = (unsigned)__cvta_generic_to_shared(&Ahs[st][arow + mt * 16][acol]);
                LDSM_X4(af[mt], p);
            }
            int brow = k16 + (lane & 15);
#pragma unroll
            for (int nt = 0; nt < 4; nt++) {
                int n0 = wn * 32 + nt * 8;
                unsigned ph = (unsigned)__cvta_generic_to_shared(&Bhs[st][brow][n0]);
                LDSM_X2T(bhf[nt], ph);
                if (use_blo) {
                    unsigned pl = (unsigned)__cvta_generic_to_shared(&Bls[st][brow][n0]);
                    LDSM_X2T(blf[nt], pl);
                }
            }
#pragma unroll
            for (int mt = 0; mt < 4; mt++)
#pragma unroll
                for (int nt = 0; nt < 4; nt++) MMA_F16(acc[mt][nt], af[mt], bhf[nt]);
            if (use_blo) {
#pragma unroll
                for (int mt = 0; mt < 4; mt++)
#pragma unroll
                    for (int nt = 0; nt < 4; nt++) MMA_F16(acc[mt][nt], af[mt], blf[nt]);
            }
        }
        __syncthreads();
        if (k0i < 2) LOAD_CHUNK(st, (k0i + 2) * 32)
    }

    int r_base = bm + wm * 64;
#pragma unroll
    for (int nt = 0; nt < 4; nt++) {
        int cl = wn * 32 + nt * 8 + ((lane & 3) << 1);
        int cg = bn + cl;
        float2 bv = *(const float2*)(bias + cg);
        float cs0 = 0.f, cs1 = 0.f, cq0 = 0.f, cq1 = 0.f;
#pragma unroll
        for (int mt = 0; mt < 4; mt++) {
            int r0 = r_base + mt * 16 + (lane >> 2);
            int r1 = r0 + 8;
            float v00 = acc[mt][nt][0] + bv.x, v01 = acc[mt][nt][1] + bv.y;
            float v10 = acc[mt][nt][2] + bv.x, v11 = acc[mt][nt][3] + bv.y;
            if (MODE == 0) {
                if (r0 < M) {
                    *(__half2*)(g_h16 + ((size_t)r0 << 7) + cg) = __floats2half2_rn(v00, v01);
                    cs0 += v00; cs1 += v01; cq0 += v00 * v00; cq1 += v01 * v01;
                }
                if (r1 < M) {
                    *(__half2*)(g_h16 + ((size_t)r1 << 7) + cg) = __floats2half2_rn(v10, v11);
                    cs0 += v10; cs1 += v11; cq0 += v10 * v10; cq1 += v11 * v11;
                }
            } else if (MODE == 1) {
                if (bn == 0) {
                    if (r0 < M) *(float2*)(g_xw + ((size_t)r0 << 7) + cl) = make_float2(v00, v01);
                    if (r1 < M) *(float2*)(g_xw + ((size_t)r1 << 7) + cl) = make_float2(v10, v11);
                } else {
                    int yc = cg - 128;
                    if (r0 < M) {
                        uint2 u = make_uint2(packerp(v00), packerp(v01));
                        *(uint2*)(g_erp + ((size_t)r0 << 9) + yc) = u;
                    }
                    if (r1 < M) {
                        uint2 u = make_uint2(packerp(v10), packerp(v11));
                        *(uint2*)(g_erp + ((size_t)r1 << 9) + yc) = u;
                    }
                }
            } else {
                if (r0 < M) {
                    float a = 0.5f * v00 * (1.0f + erff(v00 * 0.70710678118654752f));
                    float b = 0.5f * v01 * (1.0f + erff(v01 * 0.70710678118654752f));
                    *(float2*)(C + (size_t)r0 * ldc + cg) = make_float2(a, b);
                }
                if (r1 < M) {
                    float a = 0.5f * v10 * (1.0f + erff(v10 * 0.70710678118654752f));
                    float b = 0.5f * v11 * (1.0f + erff(v11 * 0.70710678118654752f));
                    *(float2*)(C + (size_t)r1 * ldc + cg) = make_float2(a, b);
                }
            }
        }
        if (MODE == 0) {
#pragma unroll
            for (int ofs = 16; ofs >= 4; ofs >>= 1) {
                cs0 += __shfl_down_sync(0xffffffffu, cs0, ofs);
                cs1 += __shfl_down_sync(0xffffffffu, cs1, ofs);
                cq0 += __shfl_down_sync(0xffffffffu, cq0, ofs);
                cq1 += __shfl_down_sync(0xffffffffu, cq1, ofs);
            }
            if ((lane >> 2) == 0) {
                atomicAdd(&g_colsum[cg], cs0);
                atomicAdd(&g_colsum[cg + 1], cs1);
                atomicAdd(&g_colsq[cg], cq0);
                atomicAdd(&g_colsq[cg + 1], cq1);
            }
        }
    }
#undef LOAD_CHUNK
}

// ---------------- BatchNorm apply + relu -> fp16 (vectorized, 4 elems/thread) ----------------
__global__ void bnrelu_kernel(const float* __restrict__ bg, const float* __restrict__ bb) {
    int i = blockIdx.x * blockDim.x + threadIdx.x;
    if (i >= NN * 32) return;
    size_t base = (size_t)i << 2;
    int c = (int)(base & 127);
    float invn = 1.0f / (float)NN;
    float4 s4 = *(const float4*)(g_colsum + c);
    float4 q4 = *(const float4*)(g_colsq + c);
    float4 gv = *(const float4*)(bg + c);
    float4 bv = *(const float4*)(bb + c);
    float mu0 = s4.x * invn, mu1 = s4.y * invn, mu2 = s4.z * invn, mu3 = s4.w * invn;
    float sc0 = rsqrtf(q4.x * invn - mu0 * mu0 + 1e-5f) * gv.x;
    float sc1 = rsqrtf(q4.y * invn - mu1 * mu1 + 1e-5f) * gv.y;
    float sc2 = rsqrtf(q4.z * invn - mu2 * mu2 + 1e-5f) * gv.z;
    float sc3 = rsqrtf(q4.w * invn - mu3 * mu3 + 1e-5f) * gv.w;
    uint2 hv = *(const uint2*)(g_h16 + base);
    float2 h0 = __half22float2(*(__half2*)&hv.x);
    float2 h1 = __half22float2(*(__half2*)&hv.y);
    float v0 = fmaxf((h0.x - mu0) * sc0 + bv.x, 0.f);
    float v1 = fmaxf((h0.y - mu1) * sc1 + bv.y, 0.f);
    float v2 = fmaxf((h1.x - mu2) * sc2 + bv.z, 0.f);
    float v3 = fmaxf((h1.y - mu3) * sc3 + bv.w, 0.f);
    __half2 o0 = __floats2half2_rn(v0, v1), o1 = __floats2half2_rn(v2, v3);
    *(uint2*)(g_hs + base) = make_uint2(*(unsigned*)&o0, *(unsigned*)&o1);
}

// ---------------- edge stage (proven R8 loop; node range [wbase, wbase+wcnt)) ----------------
__global__ void edge_kernel(int wbase, int wcnt) {
    int wi = (blockIdx.x * blockDim.x + threadIdx.x) >> 5;
    if (wi >= wcnt) return;
    int w = wbase + wi;
    int lane = threadIdx.x & 31;
    int c = lane << 2;
    int s0 = g_off[w], s1 = g_off[w + 1];
    float4 z = make_float4(0.f, 0.f, 0.f, 0.f);
    if (s0 < s1) {
        float gx = 0.f, gy = 0.f, gz = 0.f, gw = 0.f;
        float d0 = 0.f, d1 = 0.f, d2 = 0.f, d3 = 0.f;
        float n0 = 0.f, n1 = 0.f, n2 = 0.f, n3 = 0.f;
#pragma unroll 2
        for (int e = s0; e < s1; e++) {
            int2 pn = __ldg(&g_pknrm[e]);
            int pk = pn.x;
            float wn = __int_as_float(pn.y);
            int s = pk >> 2, t = pk & 3;
            float4 xj = *(const float4*)(g_xw + ((size_t)s << 7) + c);
            uint4 ep = *(const uint4*)(g_erp + ((size_t)s << 9) + (t << 7) + c);
            float2 a0 = __bfloat1622float2(*(__nv_bfloat162*)&ep.x);
            float2 a1 = __bfloat1622float2(*(__nv_bfloat162*)&ep.y);
            float2 a2 = __bfloat1622float2(*(__nv_bfloat162*)&ep.z);
            float2 a3 = __bfloat1622float2(*(__nv_bfloat162*)&ep.w);
            d0 += a0.x; n0 += a0.y;
            d1 += a1.x; n1 += a1.y;
            d2 += a2.x; n2 += a2.y;
            d3 += a3.x; n3 += a3.y;
            gx += xj.x * wn; gy += xj.y * wn; gz += xj.z * wn; gw += xj.w * wn;
        }
        z.x = gx + 0.1f * fmaxf(n0 / d0, 0.f);
        z.y = gy + 0.1f * fmaxf(n1 / d1, 0.f);
        z.z = gz + 0.1f * fmaxf(n2 / d2, 0.f);
        z.w = gw + 0.1f * fmaxf(n3 / d3, 0.f);
    }
    __half2 p0 = __floats2half2_rn(z.x, z.y);
    __half2 p1 = __floats2half2_rn(z.z, z.w);
    *(uint2*)(g_zs + ((size_t)w << 7) + c) = make_uint2(*(unsigned*)&p0, *(unsigned*)&p1);
}

// ---------------- host launcher ----------------
static void* sym_addr(const void* sym) {
    void* p = nullptr;
    cudaGetSymbolAddress(&p, sym);
    return p;
}

extern "C" void kernel_launch(void* const* d_in, const int* in_sizes, int n_in,
                              void* d_out, int out_size) {
    int ix, iei, iidx, iet, ipw, ipb, ibg, ibb, iww, iwb, iwr, iow, iob;
    if (in_sizes[1] > 1000000) {
        ix = 0; iei = 1; iidx = 2; iet = 3; ipw = 5; ipb = 6; ibg = 7; ibb = 8;
        iww = 9; iwb = 10; iwr = 11; iow = 12; iob = 13;
    } else {
        ix = 0; ipw = 2; ipb = 3; ibg = 4; ibb = 5; iww = 6; iwb = 7;
        iwr = 8; iow = 9; iob = 10; iei = 11; iet = 12; iidx = 13;
    }

    const float* x   = (const float*)d_in[ix];
    const int*   ei  = (const int*)d_in[iei];
    const int*   et  = (const int*)d_in[iet];
    const int*   idx = (const int*)d_in[iidx];
    const float* pw  = (const float*)d_in[ipw];
    const float* pb  = (const float*)d_in[ipb];
    const float* bg  = (const float*)d_in[ibg];
    const float* bb  = (const float*)d_in[ibb];
    const float* ww  = (const float*)d_in[iww];
    const float* wb  = (const float*)d_in[iwb];
    const float* wr  = (const float*)d_in[iwr];
    const float* ow  = (const float*)d_in[iow];
    const float* ob  = (const float*)d_in[iob];

    int E  = in_sizes[iei] / 2;
    int NI = out_size / 128;

    __half* xs  = (__half*)sym_addr(g_xs);
    __half* hs  = (__half*)sym_addr(g_hs);
    __half* zs  = (__half*)sym_addr(g_zs);
    float* bc0 = (float*)sym_addr(g_bc0);
    float* b01 = (float*)sym_addr(g_b01);
    __half* wc0h = (__half*)sym_addr(g_wc0h);
    __half* wc0l = (__half*)sym_addr(g_wc0l);
    __half* w01h = (__half*)sym_addr(g_w01h);
    __half* w01l = (__half*)sym_addr(g_w01l);
    __half* pwh = (__half*)sym_addr(g_pwh);
    __half* pwl = (__half*)sym_addr(g_pwl);
    __half* owh = (__half*)sym_addr(g_owh);
    __half* owl = (__half*)sym_addr(g_owl);

    // streams + events (host-side only, capture-legal)
    cudaStream_t s2, s3;
    cudaStreamCreateWithFlags(&s2, cudaStreamNonBlocking);
    cudaStreamCreateWithFlags(&s3, cudaStreamNonBlocking);
    cudaEvent_t evFork, evPrep1w, evJoin, evE0, evG0;
    cudaEventCreateWithFlags(&evFork, cudaEventDisableTiming);
    cudaEventCreateWithFlags(&evPrep1w, cudaEventDisableTiming);
    cudaEventCreateWithFlags(&evJoin, cudaEventDisableTiming);
    cudaEventCreateWithFlags(&evE0, cudaEventDisableTiming);
    cudaEventCreateWithFlags(&evG0, cudaEventDisableTiming);

    // fork
    cudaEventRecord(evFork, 0);
    cudaStreamWaitEvent(s2, evFork, 0);
    cudaStreamWaitEvent(s3, evFork, 0);

    // s2: CSR chain
    zero_kernel<<<(NN + 255) / 256, 256, 0, s2>>>();
    hist_kernel<<<(E + 255) / 256, 256, 0, s2>>>(ei, E);
    scan1_kernel<<<NB, 1024, 0, s2>>>();
    scan3_kernel<<<NB, 1024, 0, s2>>>(E);
    scatter_kernel<<<(E + 255) / 256, 256, 0, s2>>>(ei, et, E);

    // s3: weight prep (overlapped)
    prep1w_kernel<<<(181504 + 255) / 256, 256, 0, s3>>>(ow, ww, wr, wb);
    cudaEventRecord(evPrep1w, s3);

    // s2 tail: prep2 needs g_wc1 (prep1w) + after CSR
    cudaStreamWaitEvent(s2, evPrep1w, 0);
    prep2_kernel<<<(81920 + 640 + 255) / 256, 256, 0, s2>>>(ow, ob);
    cudaEventRecord(evJoin, s2);

    // main: critical-path prep (vectorized x conv + pw split) -> proj -> BN
    prep1x_kernel<<<(XS4 + 4096 + 255) / 256, 256>>>(x, pw);
    gemm_f16<0><<<dim3(1, MT), 256>>>(xs, pwh, pwl, pb, nullptr, NN, 128, 128, nullptr, 0);
    bnrelu_kernel<<<(NN * 32 + 255) / 256, 256>>>(bg, bb);

    // layer 0 GEMM needs wc0 (prep1w)
    cudaStreamWaitEvent(0, evPrep1w, 0);
    gemm_f16<1><<<dim3(5, MT), 256>>>(hs, wc0h, wc0l, bc0, nullptr, NN, 640, 0, nullptr, 0);

    // join: edge stage needs CSR + prep2 (s2) + layer0 GEMM (main)
    cudaStreamWaitEvent(0, evJoin, 0);

    // edge0 chunked; gemm-L1 chunk0 overlaps edge0 chunk1 on s3
    edge_kernel<<<(NC0 * 32 + 255) / 256, 256>>>(0, NC0);
    cudaEventRecord(evE0, 0);
    edge_kernel<<<((NN - NC0) * 32 + 255) / 256, 256>>>(NC0, NN - NC0);

    cudaStreamWaitEvent(s3, evJoin, 0);   // w01/b01 ready
    cudaStreamWaitEvent(s3, evE0, 0);     // zs rows [0, NC0) ready
    gemm_f16<1><<<dim3(5, TIL0), 256, 0, s3>>>(zs, w01h, w01l, b01, nullptr, NN, 640, 0, nullptr, 0);
    cudaEventRecord(evG0, s3);

    // main: gemm-L1 chunk1 (rows [NC0, NN)) after edge0 chunk1
    gemm_f16<1><<<dim3(5, MT - TIL0), 256>>>(zs, w01h, w01l, b01, nullptr, NN, 640, 0, nullptr, TIL0);

    // edge1 needs both gemm-L1 chunks
    cudaStreamWaitEvent(0, evG0, 0);
    edge_kernel<<<(NN * 32 + 255) / 256, 256>>>(0, NN);

    // final: out = gelu(z1[idx] @ out_w1 + ob1)
    gemm_f16<2><<<dim3(1, (NI + 127) / 128), 256>>>(zs, owh, owl, ob + 128, (float*)d_out,
                                                    NI, 128, 128, idx, 0);

    cudaEventDestroy(evFork);
    cudaEventDestroy(evPrep1w);
    cudaEventDestroy(evJoin);
    cudaEventDestroy(evE0);
    cudaEventDestroy(evG0);
    cudaStreamDestroy(s2);
    cudaStreamDestroy(s3);
}

// round 16
// speedup vs baseline: 1.3989x; 1.3989x over previous
#include <cuda_runtime.h>
#include <cuda_bf16.h>
#include <cuda_fp16.h>
#include <math.h>

#define NN 48758
#define EMAX 780000
#define NB 48   // ceil(NN/1024)

// ---------------- device scratch ----------------
__device__ __align__(16) __half g_h16[(size_t)NN * 128];       // proj output (fp16, pre-BN)
__device__ __align__(16) __half g_xs[(size_t)NN * 128];        // x as fp16 (GEMM A)
__device__ __align__(16) __half g_hs[(size_t)NN * 128];        // h post-BN/relu fp16 (GEMM A)
__device__ __align__(16) __half g_zs[(size_t)NN * 128];        // z fp16 (GEMM A)
__device__ __align__(16) float    g_xw[(size_t)NN * 128];      // fp32 xw (edge gather)
__device__ __align__(16) unsigned g_erp[(size_t)NN * 512];     // packed bf16x2 (er, p)
__device__ int   g_off[NN + 1];
__device__ int   g_cur[NN];
__device__ int   g_degsrc[NN];
__device__ int   g_degdst[NN];
__device__ float g_dinv[NN];
__device__ __align__(8) int2 g_pknrm[EMAX];                    // {pk, nrm bits}
__device__ int   g_bsum[64];
__device__ float g_colsum[128], g_colsq[128];
__device__ float g_wc1[128 * 640];
__device__ float g_bc0[640], g_bc1[640], g_b01[640];
__device__ __half g_wc0h[128 * 640], g_wc0l[128 * 640];
__device__ __half g_w01h[128 * 640], g_w01l[128 * 640];
__device__ __half g_pwh[128 * 128], g_pwl[128 * 128];
__device__ __half g_owh[128 * 128], g_owl[128 * 128];

__device__ __forceinline__ float dinvf(int dg) {
    return dg > 0 ? rsqrtf((float)dg) : 0.0f;
}

// ---------------- CSR build ----------------
__global__ void zero_kernel() {
    int i = blockIdx.x * blockDim.x + threadIdx.x;
    if (i < NN) { g_degsrc[i] = 0; g_degdst[i] = 0; }
    if (i < 128) { g_colsum[i] = 0.0f; g_colsq[i] = 0.0f; }
}

__global__ void hist_kernel(const int* __restrict__ ei, int E) {
    int e = blockIdx.x * blockDim.x + threadIdx.x;
    if (e >= E) return;
    atomicAdd(&g_degdst[ei[e]], 1);
    atomicAdd(&g_degsrc[ei[E + e]], 1);
}

// block sums of degdst + dinv table
__global__ void scan1_kernel() {
    __shared__ int sm[1024];
    int tid = threadIdx.x;
    int i = blockIdx.x * 1024 + tid;
    if (i < NN) g_dinv[i] = dinvf(g_degsrc[i]);
    int v = (i < NN) ? g_degdst[i] : 0;
    sm[tid] = v;
    __syncthreads();
    for (int ofs = 512; ofs > 0; ofs >>= 1) {
        if (tid < ofs) sm[tid] += sm[tid + ofs];
        __syncthreads();
    }
    if (tid == 0) g_bsum[blockIdx.x] = sm[0];
}

// full scan (block-local inclusive + inline scan of block sums)
__global__ void scan3_kernel(int E) {
    __shared__ int sm[1024];
    __shared__ int base_s;
    int tid = threadIdx.x;
    int i = blockIdx.x * 1024 + tid;
    int v = (i < NN) ? g_degdst[i] : 0;
    sm[tid] = v;
    if (tid == 0) {
        int b = 0;
        for (int j = 0; j < blockIdx.x; j++) b += g_bsum[j];
        base_s = b;
    }
    __syncthreads();
    for (int ofs = 1; ofs < 1024; ofs <<= 1) {
        int t = (tid >= ofs) ? sm[tid - ofs] : 0;
        __syncthreads();
        sm[tid] += t;
        __syncthreads();
    }
    if (i < NN) {
        int exv = base_s + sm[tid] - v;
        g_off[i] = exv;
        g_cur[i] = exv;
        if (i == NN - 1) g_off[NN] = E;
    }
}

__global__ void scatter_kernel(const int* __restrict__ ei, const int* __restrict__ et, int E) {
    int e = blockIdx.x * blockDim.x + threadIdx.x;
    if (e >= E) return;
    int d = ei[e];
    int s = ei[E + e];
    int slot = atomicAdd(&g_cur[d], 1);
    float nrm = g_dinv[d] * g_dinv[s];
    g_pknrm[slot] = make_int2((s << 2) | et[e], __float_as_int(nrm));
}

// ---------------- prep ----------------
__device__ __forceinline__ void split_write_h(__half* dh, __half* dl, int i, float f) {
    __half h = __float2half_rn(f);
    dh[i] = h;
    dl[i] = __float2half_rn(f - __half2float(h));
}

#define XS (NN * 128)
#define XS4 (XS / 4)
// prep1x: critical path — x conv (vectorized) + pw split (vectorized)
__global__ void prep1x_kernel(const float* __restrict__ x, const float* __restrict__ pw) {
    int i = blockIdx.x * blockDim.x + threadIdx.x;
    if (i < XS4) {
        float4 v = *(const float4*)(x + (size_t)i * 4);
        __half2 a = __floats2half2_rn(v.x, v.y);
        __half2 b = __floats2half2_rn(v.z, v.w);
        *(uint2*)(g_xs + (size_t)i * 4) = make_uint2(*(unsigned*)&a, *(unsigned*)&b);
        return;
    }
    int j = i - XS4;
    if (j < 4096) {
        float4 v = *(const float4*)(pw + j * 4);
        __half h0 = __float2half_rn(v.x), h1 = __float2half_rn(v.y);
        __half h2 = __float2half_rn(v.z), h3 = __float2half_rn(v.w);
        __half l0 = __float2half_rn(v.x - __half2float(h0));
        __half l1 = __float2half_rn(v.y - __half2float(h1));
        __half l2 = __float2half_rn(v.z - __half2float(h2));
        __half l3 = __float2half_rn(v.w - __half2float(h3));
        __half2 ph0 = __halves2half2(h0, h1), ph1 = __halves2half2(h2, h3);
        __half2 pl0 = __halves2half2(l0, l1), pl1 = __halves2half2(l2, l3);
        *(uint2*)(g_pwh + j * 4) = make_uint2(*(unsigned*)&ph0, *(unsigned*)&ph1);
        *(uint2*)(g_pwl + j * 4) = make_uint2(*(unsigned*)&pl0, *(unsigned*)&pl1);
    }
}

// prep1w: weight prep (on s3, overlapped)
__global__ void prep1w_kernel(const float* __restrict__ ow, const float* __restrict__ ww,
                              const float* __restrict__ wr, const float* __restrict__ wbv) {
    int j = blockIdx.x * blockDim.x + threadIdx.x;
    if (j < 16384) { split_write_h(g_owh, g_owl, j, ow[16384 + j]); return; }
    j -= 16384;
    if (j < 163840) {
        int l = j / 81920, rem = j % 81920, k = rem / 640, n = rem % 640;
        float v;
        if (n < 128) {
            v = ww[l * 16384 + k * 128 + n];
        } else {
            int r = (n - 128) >> 7, nn = (n - 128) & 127;
            const float* a = ww + l * 16384 + k * 128;
            const float* b = wr + (size_t)((l * 4 + r) * 128) * 128 + nn;
            float s = 0.f;
            for (int q = 0; q < 128; q++) s += a[q] * b[(size_t)q * 128];
            v = s;
        }
        if (l) g_wc1[rem] = v;
        else   split_write_h(g_wc0h, g_wc0l, rem, v);
        return;
    }
    j -= 163840;
    if (j < 1280) {
        int l = j / 640, n = j % 640;
        float v;
        if (n < 128) {
            v = wbv[l * 128 + n];
        } else {
            int r = (n - 128) >> 7, nn = (n - 128) & 127;
            const float* a = wbv + l * 128;
            const float* b = wr + (size_t)((l * 4 + r) * 128) * 128 + nn;
            float s = 0.f;
            for (int q = 0; q < 128; q++) s += a[q] * b[(size_t)q * 128];
            v = s;
        }
        (l ? g_bc1 : g_bc0)[n] = v;
    }
}

// W01 = ow0 @ wc1 (split) ; b01 = ob0 @ wc1 + bc1
__global__ void prep2_kernel(const float* __restrict__ ow, const float* __restrict__ obv) {
    int i = blockIdx.x * blockDim.x + threadIdx.x;
    if (i < 81920) {
        int k = i / 640, n = i % 640;
        const float* a = ow + k * 128;
        float s = 0.f;
        for (int q = 0; q < 128; q++) s += a[q] * g_wc1[q * 640 + n];
        split_write_h(g_w01h, g_w01l, i, s);
        return;
    }
    int n = i - 81920;
    if (n < 640) {
        float s = 0.f;
        for (int q = 0; q < 128; q++) s += obv[q] * g_wc1[q * 640 + n];
        g_b01[n] = s + g_bc1[n];
    }
}

// ---------------- tensor-core GEMM (fp16 A + split-fp16 B, cp.async) ----------------
// MODE 1, bn>0 tiles: single-MMA (no B-lo correction) — softmax-dampened path.
#define LDSM_X4(R, p) asm volatile( \
    "ldmatrix.sync.aligned.m8n8.x4.shared.b16 {%0,%1,%2,%3}, [%4];" \
    : "=r"((R)[0]), "=r"((R)[1]), "=r"((R)[2]), "=r"((R)[3]) : "r"(p))
#define LDSM_X2T(R, p) asm volatile( \
    "ldmatrix.sync.aligned.m8n8.x2.trans.shared.b16 {%0,%1}, [%2];" \
    : "=r"((R)[0]), "=r"((R)[1]) : "r"(p))
#define MMA_F16(d, a, b) asm volatile( \
    "mma.sync.aligned.m16n8k16.row.col.f32.f16.f16.f32 " \
    "{%0,%1,%2,%3},{%4,%5,%6,%7},{%8,%9},{%0,%1,%2,%3};" \
    : "+f"((d)[0]), "+f"((d)[1]), "+f"((d)[2]), "+f"((d)[3]) \
    : "r"((a)[0]), "r"((a)[1]), "r"((a)[2]), "r"((a)[3]), "r"((b)[0]), "r"((b)[1]))

__device__ __forceinline__ void cpa16(void* dst, const void* src, int sz) {
    unsigned d = (unsigned)__cvta_generic_to_shared(dst);
    asm volatile("cp.async.cg.shared.global [%0], [%1], 16, %2;" :: "r"(d), "l"(src), "r"(sz));
}
__device__ __forceinline__ void cpa_commit() { asm volatile("cp.async.commit_group;"); }

__device__ __forceinline__ unsigned packerp(float v) {
    float er = __expf(v);
    float p = v * er;
    __nv_bfloat162 t = __halves2bfloat162(__float2bfloat16_rn(er), __float2bfloat16_rn(p));
    return *reinterpret_cast<unsigned*>(&t);
}

// MODE 0: g_h16 = fp16(acc + bias) + fused column stats
// MODE 1: bn==0 -> g_xw fp32 (split-B) ; bn>0 -> g_erp packerp (single-B)
// MODE 2: C = gelu(acc + bias), rows via ridx gather on A
template <int MODE>
__global__ __launch_bounds__(256, 2)
void gemm_f16(const __half* __restrict__ A,
              const __half* __restrict__ Bh, const __half* __restrict__ Bl,
              const float* __restrict__ bias, float* __restrict__ C,
              int M, int ldb, int ldc, const int* __restrict__ ridx) {
    __shared__ __align__(16) __half Ahs[2][128][40];
    __shared__ __align__(16) __half Bhs[2][32][136];
    __shared__ __align__(16) __half Bls[2][32][136];

    int tid = threadIdx.x, lane = tid & 31, warp = tid >> 5;
    int wm = warp >> 2, wn = warp & 3;
    int bm = blockIdx.y * 128, bn = blockIdx.x * 128;
    const bool use_blo = (MODE != 1) || (bn == 0);

    float acc[4][4][4];
#pragma unroll
    for (int a = 0; a < 4; a++)
#pragma unroll
        for (int b = 0; b < 4; b++)
#pragma unroll
            for (int c = 0; c < 4; c++) acc[a][b][c] = 0.0f;

    int arr[2], asz[2];
#pragma unroll
    for (int i = 0; i < 2; i++) {
        int row = (tid + i * 256) >> 2;
        int grow = bm + row;
        bool ok = grow < M;
        arr[i] = ok ? (ridx ? ridx[grow] : grow) : 0;
        asz[i] = ok ? 16 : 0;
    }

#define LOAD_CHUNK(st, k0)                                                        \
    {                                                                             \
        _Pragma("unroll")                                                         \
        for (int i = 0; i < 2; i++) {                                             \
            int vec = tid + i * 256;                                              \
            int row = vec >> 2;                                                   \
            int c8 = (vec & 3) * 8;                                               \
            size_t go = (size_t)arr[i] * 128 + (k0) + c8;                         \
            cpa16(&Ahs[st][row][c8], A + go, asz[i]);                             \
        }                                                                         \
        _Pragma("unroll")                                                         \
        for (int i = 0; i < 2; i++) {                                             \
            int vec = tid + i * 256;                                              \
            int row = vec >> 4;                                                   \
            int c8 = (vec & 15) * 8;                                              \
            size_t go = (size_t)((k0) + row) * ldb + bn + c8;                     \
            cpa16(&Bhs[st][row][c8], Bh + go, 16);                                \
            if (use_blo) cpa16(&Bls[st][row][c8], Bl + go, 16);                   \
        }                                                                         \
        cpa_commit();                                                             \
    }

    LOAD_CHUNK(0, 0)
    LOAD_CHUNK(1, 32)

#pragma unroll
    for (int k0i = 0; k0i < 4; k0i++) {
        int st = k0i & 1;
        if (k0i < 3) asm volatile("cp.async.wait_group 1;");
        else         asm volatile("cp.async.wait_group 0;");
        __syncthreads();

#pragma unroll
        for (int k16 = 0; k16 < 32; k16 += 16) {
            unsigned af[4][4], bhf[4][2], blf[4][2];
            int arow = wm * 64 + (lane & 15);
            int acol = k16 + ((lane >> 4) << 3);
#pragma unroll
            for (int mt = 0; mt < 4; mt++) {
                unsigned p = (unsigned)__cvta_generic_to_shared(&Ahs[st][arow + mt * 16][acol]);
                LDSM_X4(af[mt], p);
            }
            int brow = k16 + (lane & 15);
#pragma unroll
            for (int nt = 0; nt < 4; nt++) {
                int n0 = wn * 32 + nt * 8;
                unsigned ph = (unsigned)__cvta_generic_to_shared(&Bhs[st][brow][n0]);
                LDSM_X2T(bhf[nt], ph);
                if (use_blo) {
                    unsigned pl = (unsigned)__cvta_generic_to_shared(&Bls[st][brow][n0]);
                    LDSM_X2T(blf[nt], pl);
                }
            }
#pragma unroll
            for (int mt = 0; mt < 4; mt++)
#pragma unroll
                for (int nt = 0; nt < 4; nt++) MMA_F16(acc[mt][nt], af[mt], bhf[nt]);
            if (use_blo) {
#pragma unroll
                for (int mt = 0; mt < 4; mt++)
#pragma unroll
                    for (int nt = 0; nt < 4; nt++) MMA_F16(acc[mt][nt], af[mt], blf[nt]);
            }
        }
        __syncthreads();
        if (k0i < 2) LOAD_CHUNK(st, (k0i + 2) * 32)
    }

    int r_base = bm + wm * 64;
#pragma unroll
    for (int nt = 0; nt < 4; nt++) {
        int cl = wn * 32 + nt * 8 + ((lane & 3) << 1);
        int cg = bn + cl;
        float2 bv = *(const float2*)(bias + cg);
        float cs0 = 0.f, cs1 = 0.f, cq0 = 0.f, cq1 = 0.f;
#pragma unroll
        for (int mt = 0; mt < 4; mt++) {
            int r0 = r_base + mt * 16 + (lane >> 2);
            int r1 = r0 + 8;
            float v00 = acc[mt][nt][0] + bv.x, v01 = acc[mt][nt][1] + bv.y;
            float v10 = acc[mt][nt][2] + bv.x, v11 = acc[mt][nt][3] + bv.y;
            if (MODE == 0) {
                if (r0 < M) {
                    *(__half2*)(g_h16 + ((size_t)r0 << 7) + cg) = __floats2half2_rn(v00, v01);
                    cs0 += v00; cs1 += v01; cq0 += v00 * v00; cq1 += v01 * v01;
                }
                if (r1 < M) {
                    *(__half2*)(g_h16 + ((size_t)r1 << 7) + cg) = __floats2half2_rn(v10, v11);
                    cs0 += v10; cs1 += v11; cq0 += v10 * v10; cq1 += v11 * v11;
                }
            } else if (MODE == 1) {
                if (bn == 0) {
                    if (r0 < M) *(float2*)(g_xw + ((size_t)r0 << 7) + cl) = make_float2(v00, v01);
                    if (r1 < M) *(float2*)(g_xw + ((size_t)r1 << 7) + cl) = make_float2(v10, v11);
                } else {
                    int yc = cg - 128;
                    if (r0 < M) {
                        uint2 u = make_uint2(packerp(v00), packerp(v01));
                        *(uint2*)(g_erp + ((size_t)r0 << 9) + yc) = u;
                    }
                    if (r1 < M) {
                        uint2 u = make_uint2(packerp(v10), packerp(v11));
                        *(uint2*)(g_erp + ((size_t)r1 << 9) + yc) = u;
                    }
                }
            } else {
                if (r0 < M) {
                    float a = 0.5f * v00 * (1.0f + erff(v00 * 0.70710678118654752f));
                    float b = 0.5f * v01 * (1.0f + erff(v01 * 0.70710678118654752f));
                    *(float2*)(C + (size_t)r0 * ldc + cg) = make_float2(a, b);
                }
                if (r1 < M) {
                    float a = 0.5f * v10 * (1.0f + erff(v10 * 0.70710678118654752f));
                    float b = 0.5f * v11 * (1.0f + erff(v11 * 0.70710678118654752f));
                    *(float2*)(C + (size_t)r1 * ldc + cg) = make_float2(a, b);
                }
            }
        }
        if (MODE == 0) {
#pragma unroll
            for (int ofs = 16; ofs >= 4; ofs >>= 1) {
                cs0 += __shfl_down_sync(0xffffffffu, cs0, ofs);
                cs1 += __shfl_down_sync(0xffffffffu, cs1, ofs);
                cq0 += __shfl_down_sync(0xffffffffu, cq0, ofs);
                cq1 += __shfl_down_sync(0xffffffffu, cq1, ofs);
            }
            if ((lane >> 2) == 0) {
                atomicAdd(&g_colsum[cg], cs0);
                atomicAdd(&g_colsum[cg + 1], cs1);
                atomicAdd(&g_colsq[cg], cq0);
                atomicAdd(&g_colsq[cg + 1], cq1);
            }
        }
    }
#undef LOAD_CHUNK
}

// ---------------- BatchNorm apply + relu -> fp16 (vectorized, 4 elems/thread) ----------------
__global__ void bnrelu_kernel(const float* __restrict__ bg, const float* __restrict__ bb) {
    int i = blockIdx.x * blockDim.x + threadIdx.x;
    if (i >= NN * 32) return;
    size_t base = (size_t)i << 2;
    int c = (int)(base & 127);
    float invn = 1.0f / (float)NN;
    float4 s4 = *(const float4*)(g_colsum + c);
    float4 q4 = *(const float4*)(g_colsq + c);
    float4 gv = *(const float4*)(bg + c);
    float4 bv = *(const float4*)(bb + c);
    float mu0 = s4.x * invn, mu1 = s4.y * invn, mu2 = s4.z * invn, mu3 = s4.w * invn;
    float sc0 = rsqrtf(q4.x * invn - mu0 * mu0 + 1e-5f) * gv.x;
    float sc1 = rsqrtf(q4.y * invn - mu1 * mu1 + 1e-5f) * gv.y;
    float sc2 = rsqrtf(q4.z * invn - mu2 * mu2 + 1e-5f) * gv.z;
    float sc3 = rsqrtf(q4.w * invn - mu3 * mu3 + 1e-5f) * gv.w;
    uint2 hv = *(const uint2*)(g_h16 + base);
    float2 h0 = __half22float2(*(__half2*)&hv.x);
    float2 h1 = __half22float2(*(__half2*)&hv.y);
    float v0 = fmaxf((h0.x - mu0) * sc0 + bv.x, 0.f);
    float v1 = fmaxf((h0.y - mu1) * sc1 + bv.y, 0.f);
    float v2 = fmaxf((h1.x - mu2) * sc2 + bv.z, 0.f);
    float v3 = fmaxf((h1.y - mu3) * sc3 + bv.w, 0.f);
    __half2 o0 = __floats2half2_rn(v0, v1), o1 = __floats2half2_rn(v2, v3);
    *(uint2*)(g_hs + base) = make_uint2(*(unsigned*)&o0, *(unsigned*)&o1);
}

// ---------------- edge stage (proven R8 loop; int2 merged metadata) ----------------
__global__ void edge_kernel() {
    int w = (blockIdx.x * blockDim.x + threadIdx.x) >> 5;
    if (w >= NN) return;
    int lane = threadIdx.x & 31;
    int c = lane << 2;
    int s0 = g_off[w], s1 = g_off[w + 1];
    float4 z = make_float4(0.f, 0.f, 0.f, 0.f);
    if (s0 < s1) {
        float gx = 0.f, gy = 0.f, gz = 0.f, gw = 0.f;
        float d0 = 0.f, d1 = 0.f, d2 = 0.f, d3 = 0.f;
        float n0 = 0.f, n1 = 0.f, n2 = 0.f, n3 = 0.f;
#pragma unroll 2
        for (int e = s0; e < s1; e++) {
            int2 pn = __ldg(&g_pknrm[e]);
            int pk = pn.x;
            float wn = __int_as_float(pn.y);
            int s = pk >> 2, t = pk & 3;
            float4 xj = *(const float4*)(g_xw + ((size_t)s << 7) + c);
            uint4 ep = *(const uint4*)(g_erp + ((size_t)s << 9) + (t << 7) + c);
            float2 a0 = __bfloat1622float2(*(__nv_bfloat162*)&ep.x);
            float2 a1 = __bfloat1622float2(*(__nv_bfloat162*)&ep.y);
            float2 a2 = __bfloat1622float2(*(__nv_bfloat162*)&ep.z);
            float2 a3 = __bfloat1622float2(*(__nv_bfloat162*)&ep.w);
            d0 += a0.x; n0 += a0.y;
            d1 += a1.x; n1 += a1.y;
            d2 += a2.x; n2 += a2.y;
            d3 += a3.x; n3 += a3.y;
            gx += xj.x * wn; gy += xj.y * wn; gz += xj.z * wn; gw += xj.w * wn;
        }
        z.x = gx + 0.1f * fmaxf(n0 / d0, 0.f);
        z.y = gy + 0.1f * fmaxf(n1 / d1, 0.f);
        z.z = gz + 0.1f * fmaxf(n2 / d2, 0.f);
        z.w = gw + 0.1f * fmaxf(n3 / d3, 0.f);
    }
    __half2 p0 = __floats2half2_rn(z.x, z.y);
    __half2 p1 = __floats2half2_rn(z.z, z.w);
    *(uint2*)(g_zs + ((size_t)w << 7) + c) = make_uint2(*(unsigned*)&p0, *(unsigned*)&p1);
}

// ---------------- host launcher ----------------
static void* sym_addr(const void* sym) {
    void* p = nullptr;
    cudaGetSymbolAddress(&p, sym);
    return p;
}

extern "C" void kernel_launch(void* const* d_in, const int* in_sizes, int n_in,
                              void* d_out, int out_size) {
    int ix, iei, iidx, iet, ipw, ipb, ibg, ibb, iww, iwb, iwr, iow, iob;
    if (in_sizes[1] > 1000000) {
        ix = 0; iei = 1; iidx = 2; iet = 3; ipw = 5; ipb = 6; ibg = 7; ibb = 8;
        iww = 9; iwb = 10; iwr = 11; iow = 12; iob = 13;
    } else {
        ix = 0; ipw = 2; ipb = 3; ibg = 4; ibb = 5; iww = 6; iwb = 7;
        iwr = 8; iow = 9; iob = 10; iei = 11; iet = 12; iidx = 13;
    }

    const float* x   = (const float*)d_in[ix];
    const int*   ei  = (const int*)d_in[iei];
    const int*   et  = (const int*)d_in[iet];
    const int*   idx = (const int*)d_in[iidx];
    const float* pw  = (const float*)d_in[ipw];
    const float* pb  = (const float*)d_in[ipb];
    const float* bg  = (const float*)d_in[ibg];
    const float* bb  = (const float*)d_in[ibb];
    const float* ww  = (const float*)d_in[iww];
    const float* wb  = (const float*)d_in[iwb];
    const float* wr  = (const float*)d_in[iwr];
    const float* ow  = (const float*)d_in[iow];
    const float* ob  = (const float*)d_in[iob];

    int E  = in_sizes[iei] / 2;
    int NI = out_size / 128;

    __half* xs  = (__half*)sym_addr(g_xs);
    __half* hs  = (__half*)sym_addr(g_hs);
    __half* zs  = (__half*)sym_addr(g_zs);
    float* bc0 = (float*)sym_addr(g_bc0);
    float* b01 = (float*)sym_addr(g_b01);
    __half* wc0h = (__half*)sym_addr(g_wc0h);
    __half* wc0l = (__half*)sym_addr(g_wc0l);
    __half* w01h = (__half*)sym_addr(g_w01h);
    __half* w01l = (__half*)sym_addr(g_w01l);
    __half* pwh = (__half*)sym_addr(g_pwh);
    __half* pwl = (__half*)sym_addr(g_pwl);
    __half* owh = (__half*)sym_addr(g_owh);
    __half* owl = (__half*)sym_addr(g_owl);

    // streams + events (host-side only, capture-legal)
    cudaStream_t s2, s3;
    cudaStreamCreateWithFlags(&s2, cudaStreamNonBlocking);
    cudaStreamCreateWithFlags(&s3, cudaStreamNonBlocking);
    cudaEvent_t evFork, evPrep1w, evJoin;
    cudaEventCreateWithFlags(&evFork, cudaEventDisableTiming);
    cudaEventCreateWithFlags(&evPrep1w, cudaEventDisableTiming);
    cudaEventCreateWithFlags(&evJoin, cudaEventDisableTiming);

    // fork
    cudaEventRecord(evFork, 0);
    cudaStreamWaitEvent(s2, evFork, 0);
    cudaStreamWaitEvent(s3, evFork, 0);

    // s2: CSR chain
    zero_kernel<<<(NN + 255) / 256, 256, 0, s2>>>();
    hist_kernel<<<(E + 255) / 256, 256, 0, s2>>>(ei, E);
    scan1_kernel<<<NB, 1024, 0, s2>>>();
    scan3_kernel<<<NB, 1024, 0, s2>>>(E);
    scatter_kernel<<<(E + 255) / 256, 256, 0, s2>>>(ei, et, E);

    // s3: weight prep (overlapped)
    prep1w_kernel<<<(181504 + 255) / 256, 256, 0, s3>>>(ow, ww, wr, wb);
    cudaEventRecord(evPrep1w, s3);

    // s2 tail: prep2 needs g_wc1 (prep1w) + after CSR
    cudaStreamWaitEvent(s2, evPrep1w, 0);
    prep2_kernel<<<(81920 + 640 + 255) / 256, 256, 0, s2>>>(ow, ob);
    cudaEventRecord(evJoin, s2);

    // main: critical-path prep (vectorized x conv + pw split) -> proj -> BN
    prep1x_kernel<<<(XS4 + 4096 + 255) / 256, 256>>>(x, pw);
    int mtiles = (NN + 127) / 128;
    gemm_f16<0><<<dim3(1, mtiles), 256>>>(xs, pwh, pwl, pb, nullptr, NN, 128, 128, nullptr);
    bnrelu_kernel<<<(NN * 32 + 255) / 256, 256>>>(bg, bb);

    // layer 0 GEMM needs wc0 (prep1w)
    cudaStreamWaitEvent(0, evPrep1w, 0);
    gemm_f16<1><<<dim3(5, mtiles), 256>>>(hs, wc0h, wc0l, bc0, nullptr, NN, 640, 0, nullptr);

    // join: edge stage needs CSR + prep2 (s2) + layer0 GEMM (main)
    cudaStreamWaitEvent(0, evJoin, 0);
    edge_kernel<<<(NN * 32 + 255) / 256, 256>>>();

    // layer 1 (fused layer0-out)
    gemm_f16<1><<<dim3(5, mtiles), 256>>>(zs, w01h, w01l, b01, nullptr, NN, 640, 0, nullptr);
    edge_kernel<<<(NN * 32 + 255) / 256, 256>>>();

    // final: out = gelu(z1[idx] @ out_w1 + ob1)
    gemm_f16<2><<<dim3(1, (NI + 127) / 128), 256>>>(zs, owh, owl, ob + 128, (float*)d_out,
                                                    NI, 128, 128, idx);

    cudaEventDestroy(evFork);
    cudaEventDestroy(evPrep1w);
    cudaEventDestroy(evJoin);
    cudaStreamDestroy(s2);
    cudaStreamDestroy(s3);
}

// round 17
// speedup vs baseline: 1.4448x; 1.0328x over previous
#include <cuda_runtime.h>
#include <cuda_bf16.h>
#include <cuda_fp16.h>
#include <math.h>

#define NN 48758
#define EMAX 780000
#define NB 48   // ceil(NN/1024)

// ---------------- device scratch ----------------
__device__ __align__(16) __half g_h16[(size_t)NN * 128];       // proj output (fp16, pre-BN)
__device__ __align__(16) __half g_xs[(size_t)NN * 128];        // x as fp16 (GEMM A)
__device__ __align__(16) __half g_hs[(size_t)NN * 128];        // h post-BN/relu fp16 (GEMM A)
__device__ __align__(16) __half g_zs[(size_t)NN * 128];        // z fp16 (GEMM A)
__device__ __align__(16) float    g_xw[(size_t)NN * 128];      // fp32 xw (edge gather)
__device__ __align__(16) unsigned g_erp[(size_t)NN * 512];     // packed bf16x2 (er, p)
__device__ int   g_off[NN + 1];
__device__ int   g_cur[NN];
__device__ int   g_degsrc[NN];
__device__ int   g_degdst[NN];
__device__ float g_dinv[NN];
__device__ __align__(8) int2 g_pknrm[EMAX];                    // {pk, nrm bits}
__device__ int   g_bsum[64];
__device__ float g_colsum[128], g_colsq[128];
__device__ float g_wc1[128 * 640];
__device__ float g_bc0[640], g_bc1[640], g_b01[640];
__device__ __half g_wc0h[128 * 640], g_wc0l[128 * 640];
__device__ __half g_w01h[128 * 640], g_w01l[128 * 640];
__device__ __half g_pwh[128 * 128], g_pwl[128 * 128];
__device__ __half g_owh[128 * 128], g_owl[128 * 128];

__device__ __forceinline__ float dinvf(int dg) {
    return dg > 0 ? rsqrtf((float)dg) : 0.0f;
}

// ---------------- CSR build ----------------
__global__ void zero_kernel() {
    int i = blockIdx.x * blockDim.x + threadIdx.x;
    if (i < NN) { g_degsrc[i] = 0; g_degdst[i] = 0; }
    if (i < 128) { g_colsum[i] = 0.0f; g_colsq[i] = 0.0f; }
}

__global__ void hist_kernel(const int* __restrict__ ei, int E) {
    int e = blockIdx.x * blockDim.x + threadIdx.x;
    if (e >= E) return;
    atomicAdd(&g_degdst[ei[e]], 1);
    atomicAdd(&g_degsrc[ei[E + e]], 1);
}

// block sums of degdst + dinv table
__global__ void scan1_kernel() {
    __shared__ int sm[1024];
    int tid = threadIdx.x;
    int i = blockIdx.x * 1024 + tid;
    if (i < NN) g_dinv[i] = dinvf(g_degsrc[i]);
    int v = (i < NN) ? g_degdst[i] : 0;
    sm[tid] = v;
    __syncthreads();
    for (int ofs = 512; ofs > 0; ofs >>= 1) {
        if (tid < ofs) sm[tid] += sm[tid + ofs];
        __syncthreads();
    }
    if (tid == 0) g_bsum[blockIdx.x] = sm[0];
}

// full scan (block-local inclusive + inline scan of block sums)
__global__ void scan3_kernel(int E) {
    __shared__ int sm[1024];
    __shared__ int base_s;
    int tid = threadIdx.x;
    int i = blockIdx.x * 1024 + tid;
    int v = (i < NN) ? g_degdst[i] : 0;
    sm[tid] = v;
    if (tid == 0) {
        int b = 0;
        for (int j = 0; j < blockIdx.x; j++) b += g_bsum[j];
        base_s = b;
    }
    __syncthreads();
    for (int ofs = 1; ofs < 1024; ofs <<= 1) {
        int t = (tid >= ofs) ? sm[tid - ofs] : 0;
        __syncthreads();
        sm[tid] += t;
        __syncthreads();
    }
    if (i < NN) {
        int exv = base_s + sm[tid] - v;
        g_off[i] = exv;
        g_cur[i] = exv;
        if (i == NN - 1) g_off[NN] = E;
    }
}

__global__ void scatter_kernel(const int* __restrict__ ei, const int* __restrict__ et, int E) {
    int e = blockIdx.x * blockDim.x + threadIdx.x;
    if (e >= E) return;
    int d = ei[e];
    int s = ei[E + e];
    int slot = atomicAdd(&g_cur[d], 1);
    float nrm = g_dinv[d] * g_dinv[s];
    g_pknrm[slot] = make_int2((s << 2) | et[e], __float_as_int(nrm));
}

// ---------------- prep ----------------
__device__ __forceinline__ void split_write_h(__half* dh, __half* dl, int i, float f) {
    __half h = __float2half_rn(f);
    dh[i] = h;
    dl[i] = __float2half_rn(f - __half2float(h));
}

#define XS (NN * 128)
#define XS4 (XS / 4)
// prep1x: critical path — x conv (vectorized) + pw split (vectorized)
__global__ void prep1x_kernel(const float* __restrict__ x, const float* __restrict__ pw) {
    int i = blockIdx.x * blockDim.x + threadIdx.x;
    if (i < XS4) {
        float4 v = *(const float4*)(x + (size_t)i * 4);
        __half2 a = __floats2half2_rn(v.x, v.y);
        __half2 b = __floats2half2_rn(v.z, v.w);
        *(uint2*)(g_xs + (size_t)i * 4) = make_uint2(*(unsigned*)&a, *(unsigned*)&b);
        return;
    }
    int j = i - XS4;
    if (j < 4096) {
        float4 v = *(const float4*)(pw + j * 4);
        __half h0 = __float2half_rn(v.x), h1 = __float2half_rn(v.y);
        __half h2 = __float2half_rn(v.z), h3 = __float2half_rn(v.w);
        __half l0 = __float2half_rn(v.x - __half2float(h0));
        __half l1 = __float2half_rn(v.y - __half2float(h1));
        __half l2 = __float2half_rn(v.z - __half2float(h2));
        __half l3 = __float2half_rn(v.w - __half2float(h3));
        __half2 ph0 = __halves2half2(h0, h1), ph1 = __halves2half2(h2, h3);
        __half2 pl0 = __halves2half2(l0, l1), pl1 = __halves2half2(l2, l3);
        *(uint2*)(g_pwh + j * 4) = make_uint2(*(unsigned*)&ph0, *(unsigned*)&ph1);
        *(uint2*)(g_pwl + j * 4) = make_uint2(*(unsigned*)&pl0, *(unsigned*)&pl1);
    }
}

// prep1w: weight prep (on s3, overlapped)
__global__ void prep1w_kernel(const float* __restrict__ ow, const float* __restrict__ ww,
                              const float* __restrict__ wr, const float* __restrict__ wbv) {
    int j = blockIdx.x * blockDim.x + threadIdx.x;
    if (j < 16384) { split_write_h(g_owh, g_owl, j, ow[16384 + j]); return; }
    j -= 16384;
    if (j < 163840) {
        int l = j / 81920, rem = j % 81920, k = rem / 640, n = rem % 640;
        float v;
        if (n < 128) {
            v = ww[l * 16384 + k * 128 + n];
        } else {
            int r = (n - 128) >> 7, nn = (n - 128) & 127;
            const float* a = ww + l * 16384 + k * 128;
            const float* b = wr + (size_t)((l * 4 + r) * 128) * 128 + nn;
            float s = 0.f;
            for (int q = 0; q < 128; q++) s += a[q] * b[(size_t)q * 128];
            v = s;
        }
        if (l) g_wc1[rem] = v;
        else   split_write_h(g_wc0h, g_wc0l, rem, v);
        return;
    }
    j -= 163840;
    if (j < 1280) {
        int l = j / 640, n = j % 640;
        float v;
        if (n < 128) {
            v = wbv[l * 128 + n];
        } else {
            int r = (n - 128) >> 7, nn = (n - 128) & 127;
            const float* a = wbv + l * 128;
            const float* b = wr + (size_t)((l * 4 + r) * 128) * 128 + nn;
            float s = 0.f;
            for (int q = 0; q < 128; q++) s += a[q] * b[(size_t)q * 128];
            v = s;
        }
        (l ? g_bc1 : g_bc0)[n] = v;
    }
}

// W01 = ow0 @ wc1 (split) ; b01 = ob0 @ wc1 + bc1
__global__ void prep2_kernel(const float* __restrict__ ow, const float* __restrict__ obv) {
    int i = blockIdx.x * blockDim.x + threadIdx.x;
    if (i < 81920) {
        int k = i / 640, n = i % 640;
        const float* a = ow + k * 128;
        float s = 0.f;
        for (int q = 0; q < 128; q++) s += a[q] * g_wc1[q * 640 + n];
        split_write_h(g_w01h, g_w01l, i, s);
        return;
    }
    int n = i - 81920;
    if (n < 640) {
        float s = 0.f;
        for (int q = 0; q < 128; q++) s += obv[q] * g_wc1[q * 640 + n];
        g_b01[n] = s + g_bc1[n];
    }
}

// ---------------- tensor-core GEMM (fp16 A, cp.async) ----------------
// B-lo correction only in MODE 2 (final output GEMM); all intermediate GEMMs
// use single-fp16 B (BN self-consistency + softmax dampening absorb the error).
#define LDSM_X4(R, p) asm volatile( \
    "ldmatrix.sync.aligned.m8n8.x4.shared.b16 {%0,%1,%2,%3}, [%4];" \
    : "=r"((R)[0]), "=r"((R)[1]), "=r"((R)[2]), "=r"((R)[3]) : "r"(p))
#define LDSM_X2T(R, p) asm volatile( \
    "ldmatrix.sync.aligned.m8n8.x2.trans.shared.b16 {%0,%1}, [%2];" \
    : "=r"((R)[0]), "=r"((R)[1]) : "r"(p))
#define MMA_F16(d, a, b) asm volatile( \
    "mma.sync.aligned.m16n8k16.row.col.f32.f16.f16.f32 " \
    "{%0,%1,%2,%3},{%4,%5,%6,%7},{%8,%9},{%0,%1,%2,%3};" \
    : "+f"((d)[0]), "+f"((d)[1]), "+f"((d)[2]), "+f"((d)[3]) \
    : "r"((a)[0]), "r"((a)[1]), "r"((a)[2]), "r"((a)[3]), "r"((b)[0]), "r"((b)[1]))

__device__ __forceinline__ void cpa16(void* dst, const void* src, int sz) {
    unsigned d = (unsigned)__cvta_generic_to_shared(dst);
    asm volatile("cp.async.cg.shared.global [%0], [%1], 16, %2;" :: "r"(d), "l"(src), "r"(sz));
}
__device__ __forceinline__ void cpa_commit() { asm volatile("cp.async.commit_group;"); }

__device__ __forceinline__ unsigned packerp(float v) {
    float er = __expf(v);
    float p = v * er;
    __nv_bfloat162 t = __halves2bfloat162(__float2bfloat16_rn(er), __float2bfloat16_rn(p));
    return *reinterpret_cast<unsigned*>(&t);
}

// MODE 0: g_h16 = fp16(acc + bias) + fused column stats
// MODE 1: bn==0 -> g_xw fp32 ; bn>0 -> g_erp packerp
// MODE 2: C = gelu(acc + bias), rows via ridx gather on A (split-B)
template <int MODE>
__global__ __launch_bounds__(256, 2)
void gemm_f16(const __half* __restrict__ A,
              const __half* __restrict__ Bh, const __half* __restrict__ Bl,
              const float* __restrict__ bias, float* __restrict__ C,
              int M, int ldb, int ldc, const int* __restrict__ ridx) {
    __shared__ __align__(16) __half Ahs[2][128][40];
    __shared__ __align__(16) __half Bhs[2][32][136];
    __shared__ __align__(16) __half Bls[2][32][136];

    int tid = threadIdx.x, lane = tid & 31, warp = tid >> 5;
    int wm = warp >> 2, wn = warp & 3;
    int bm = blockIdx.y * 128, bn = blockIdx.x * 128;
    const bool use_blo = (MODE == 2);

    float acc[4][4][4];
#pragma unroll
    for (int a = 0; a < 4; a++)
#pragma unroll
        for (int b = 0; b < 4; b++)
#pragma unroll
            for (int c = 0; c < 4; c++) acc[a][b][c] = 0.0f;

    int arr[2], asz[2];
#pragma unroll
    for (int i = 0; i < 2; i++) {
        int row = (tid + i * 256) >> 2;
        int grow = bm + row;
        bool ok = grow < M;
        arr[i] = ok ? (ridx ? ridx[grow] : grow) : 0;
        asz[i] = ok ? 16 : 0;
    }

#define LOAD_CHUNK(st, k0)                                                        \
    {                                                                             \
        _Pragma("unroll")                                                         \
        for (int i = 0; i < 2; i++) {                                             \
            int vec = tid + i * 256;                                              \
            int row = vec >> 2;                                                   \
            int c8 = (vec & 3) * 8;                                               \
            size_t go = (size_t)arr[i] * 128 + (k0) + c8;                         \
            cpa16(&Ahs[st][row][c8], A + go, asz[i]);                             \
        }                                                                         \
        _Pragma("unroll")                                                         \
        for (int i = 0; i < 2; i++) {                                             \
            int vec = tid + i * 256;                                              \
            int row = vec >> 4;                                                   \
            int c8 = (vec & 15) * 8;                                              \
            size_t go = (size_t)((k0) + row) * ldb + bn + c8;                     \
            cpa16(&Bhs[st][row][c8], Bh + go, 16);                                \
            if (use_blo) cpa16(&Bls[st][row][c8], Bl + go, 16);                   \
        }                                                                         \
        cpa_commit();                                                             \
    }

    LOAD_CHUNK(0, 0)
    LOAD_CHUNK(1, 32)

#pragma unroll
    for (int k0i = 0; k0i < 4; k0i++) {
        int st = k0i & 1;
        if (k0i < 3) asm volatile("cp.async.wait_group 1;");
        else         asm volatile("cp.async.wait_group 0;");
        __syncthreads();

#pragma unroll
        for (int k16 = 0; k16 < 32; k16 += 16) {
            unsigned af[4][4], bhf[4][2], blf[4][2];
            int arow = wm * 64 + (lane & 15);
            int acol = k16 + ((lane >> 4) << 3);
#pragma unroll
            for (int mt = 0; mt < 4; mt++) {
                unsigned p = (unsigned)__cvta_generic_to_shared(&Ahs[st][arow + mt * 16][acol]);
                LDSM_X4(af[mt], p);
            }
            int brow = k16 + (lane & 15);
#pragma unroll
            for (int nt = 0; nt < 4; nt++) {
                int n0 = wn * 32 + nt * 8;
                unsigned ph = (unsigned)__cvta_generic_to_shared(&Bhs[st][brow][n0]);
                LDSM_X2T(bhf[nt], ph);
                if (use_blo) {
                    unsigned pl = (unsigned)__cvta_generic_to_shared(&Bls[st][brow][n0]);
                    LDSM_X2T(blf[nt], pl);
                }
            }
#pragma unroll
            for (int mt = 0; mt < 4; mt++)
#pragma unroll
                for (int nt = 0; nt < 4; nt++) MMA_F16(acc[mt][nt], af[mt], bhf[nt]);
            if (use_blo) {
#pragma unroll
                for (int mt = 0; mt < 4; mt++)
#pragma unroll
                    for (int nt = 0; nt < 4; nt++) MMA_F16(acc[mt][nt], af[mt], blf[nt]);
            }
        }
        __syncthreads();
        if (k0i < 2) LOAD_CHUNK(st, (k0i + 2) * 32)
    }

    int r_base = bm + wm * 64;
#pragma unroll
    for (int nt = 0; nt < 4; nt++) {
        int cl = wn * 32 + nt * 8 + ((lane & 3) << 1);
        int cg = bn + cl;
        float2 bv = *(const float2*)(bias + cg);
        float cs0 = 0.f, cs1 = 0.f, cq0 = 0.f, cq1 = 0.f;
#pragma unroll
        for (int mt = 0; mt < 4; mt++) {
            int r0 = r_base + mt * 16 + (lane >> 2);
            int r1 = r0 + 8;
            float v00 = acc[mt][nt][0] + bv.x, v01 = acc[mt][nt][1] + bv.y;
            float v10 = acc[mt][nt][2] + bv.x, v11 = acc[mt][nt][3] + bv.y;
            if (MODE == 0) {
                if (r0 < M) {
                    *(__half2*)(g_h16 + ((size_t)r0 << 7) + cg) = __floats2half2_rn(v00, v01);
                    cs0 += v00; cs1 += v01; cq0 += v00 * v00; cq1 += v01 * v01;
                }
                if (r1 < M) {
                    *(__half2*)(g_h16 + ((size_t)r1 << 7) + cg) = __floats2half2_rn(v10, v11);
                    cs0 += v10; cs1 += v11; cq0 += v10 * v10; cq1 += v11 * v11;
                }
            } else if (MODE == 1) {
                if (bn == 0) {
                    if (r0 < M) *(float2*)(g_xw + ((size_t)r0 << 7) + cl) = make_float2(v00, v01);
                    if (r1 < M) *(float2*)(g_xw + ((size_t)r1 << 7) + cl) = make_float2(v10, v11);
                } else {
                    int yc = cg - 128;
                    if (r0 < M) {
                        uint2 u = make_uint2(packerp(v00), packerp(v01));
                        *(uint2*)(g_erp + ((size_t)r0 << 9) + yc) = u;
                    }
                    if (r1 < M) {
                        uint2 u = make_uint2(packerp(v10), packerp(v11));
                        *(uint2*)(g_erp + ((size_t)r1 << 9) + yc) = u;
                    }
                }
            } else {
                if (r0 < M) {
                    float a = 0.5f * v00 * (1.0f + erff(v00 * 0.70710678118654752f));
                    float b = 0.5f * v01 * (1.0f + erff(v01 * 0.70710678118654752f));
                    *(float2*)(C + (size_t)r0 * ldc + cg) = make_float2(a, b);
                }
                if (r1 < M) {
                    float a = 0.5f * v10 * (1.0f + erff(v10 * 0.70710678118654752f));
                    float b = 0.5f * v11 * (1.0f + erff(v11 * 0.70710678118654752f));
                    *(float2*)(C + (size_t)r1 * ldc + cg) = make_float2(a, b);
                }
            }
        }
        if (MODE == 0) {
#pragma unroll
            for (int ofs = 16; ofs >= 4; ofs >>= 1) {
                cs0 += __shfl_down_sync(0xffffffffu, cs0, ofs);
                cs1 += __shfl_down_sync(0xffffffffu, cs1, ofs);
                cq0 += __shfl_down_sync(0xffffffffu, cq0, ofs);
                cq1 += __shfl_down_sync(0xffffffffu, cq1, ofs);
            }
            if ((lane >> 2) == 0) {
                atomicAdd(&g_colsum[cg], cs0);
                atomicAdd(&g_colsum[cg + 1], cs1);
                atomicAdd(&g_colsq[cg], cq0);
                atomicAdd(&g_colsq[cg + 1], cq1);
            }
        }
    }
#undef LOAD_CHUNK
}

// ---------------- BatchNorm apply + relu -> fp16 (vectorized, 4 elems/thread) ----------------
__global__ void bnrelu_kernel(const float* __restrict__ bg, const float* __restrict__ bb) {
    int i = blockIdx.x * blockDim.x + threadIdx.x;
    if (i >= NN * 32) return;
    size_t base = (size_t)i << 2;
    int c = (int)(base & 127);
    float invn = 1.0f / (float)NN;
    float4 s4 = *(const float4*)(g_colsum + c);
    float4 q4 = *(const float4*)(g_colsq + c);
    float4 gv = *(const float4*)(bg + c);
    float4 bv = *(const float4*)(bb + c);
    float mu0 = s4.x * invn, mu1 = s4.y * invn, mu2 = s4.z * invn, mu3 = s4.w * invn;
    float sc0 = rsqrtf(q4.x * invn - mu0 * mu0 + 1e-5f) * gv.x;
    float sc1 = rsqrtf(q4.y * invn - mu1 * mu1 + 1e-5f) * gv.y;
    float sc2 = rsqrtf(q4.z * invn - mu2 * mu2 + 1e-5f) * gv.z;
    float sc3 = rsqrtf(q4.w * invn - mu3 * mu3 + 1e-5f) * gv.w;
    uint2 hv = *(const uint2*)(g_h16 + base);
    float2 h0 = __half22float2(*(__half2*)&hv.x);
    float2 h1 = __half22float2(*(__half2*)&hv.y);
    float v0 = fmaxf((h0.x - mu0) * sc0 + bv.x, 0.f);
    float v1 = fmaxf((h0.y - mu1) * sc1 + bv.y, 0.f);
    float v2 = fmaxf((h1.x - mu2) * sc2 + bv.z, 0.f);
    float v3 = fmaxf((h1.y - mu3) * sc3 + bv.w, 0.f);
    __half2 o0 = __floats2half2_rn(v0, v1), o1 = __floats2half2_rn(v2, v3);
    *(uint2*)(g_hs + base) = make_uint2(*(unsigned*)&o0, *(unsigned*)&o1);
}

// ---------------- edge stage (proven R16 loop: int2 metadata + fp32 xw + bf16 erp) ----------------
__global__ void edge_kernel() {
    int w = (blockIdx.x * blockDim.x + threadIdx.x) >> 5;
    if (w >= NN) return;
    int lane = threadIdx.x & 31;
    int c = lane << 2;
    int s0 = g_off[w], s1 = g_off[w + 1];
    float4 z = make_float4(0.f, 0.f, 0.f, 0.f);
    if (s0 < s1) {
        float gx = 0.f, gy = 0.f, gz = 0.f, gw = 0.f;
        float d0 = 0.f, d1 = 0.f, d2 = 0.f, d3 = 0.f;
        float n0 = 0.f, n1 = 0.f, n2 = 0.f, n3 = 0.f;
#pragma unroll 2
        for (int e = s0; e < s1; e++) {
            int2 pn = __ldg(&g_pknrm[e]);
            int pk = pn.x;
            float wn = __int_as_float(pn.y);
            int s = pk >> 2, t = pk & 3;
            float4 xj = *(const float4*)(g_xw + ((size_t)s << 7) + c);
            uint4 ep = *(const uint4*)(g_erp + ((size_t)s << 9) + (t << 7) + c);
            float2 a0 = __bfloat1622float2(*(__nv_bfloat162*)&ep.x);
            float2 a1 = __bfloat1622float2(*(__nv_bfloat162*)&ep.y);
            float2 a2 = __bfloat1622float2(*(__nv_bfloat162*)&ep.z);
            float2 a3 = __bfloat1622float2(*(__nv_bfloat162*)&ep.w);
            d0 += a0.x; n0 += a0.y;
            d1 += a1.x; n1 += a1.y;
            d2 += a2.x; n2 += a2.y;
            d3 += a3.x; n3 += a3.y;
            gx += xj.x * wn; gy += xj.y * wn; gz += xj.z * wn; gw += xj.w * wn;
        }
        z.x = gx + 0.1f * fmaxf(n0 / d0, 0.f);
        z.y = gy + 0.1f * fmaxf(n1 / d1, 0.f);
        z.z = gz + 0.1f * fmaxf(n2 / d2, 0.f);
        z.w = gw + 0.1f * fmaxf(n3 / d3, 0.f);
    }
    __half2 p0 = __floats2half2_rn(z.x, z.y);
    __half2 p1 = __floats2half2_rn(z.z, z.w);
    *(uint2*)(g_zs + ((size_t)w << 7) + c) = make_uint2(*(unsigned*)&p0, *(unsigned*)&p1);
}

// ---------------- host launcher ----------------
static void* sym_addr(const void* sym) {
    void* p = nullptr;
    cudaGetSymbolAddress(&p, sym);
    return p;
}

extern "C" void kernel_launch(void* const* d_in, const int* in_sizes, int n_in,
                              void* d_out, int out_size) {
    int ix, iei, iidx, iet, ipw, ipb, ibg, ibb, iww, iwb, iwr, iow, iob;
    if (in_sizes[1] > 1000000) {
        ix = 0; iei = 1; iidx = 2; iet = 3; ipw = 5; ipb = 6; ibg = 7; ibb = 8;
        iww = 9; iwb = 10; iwr = 11; iow = 12; iob = 13;
    } else {
        ix = 0; ipw = 2; ipb = 3; ibg = 4; ibb = 5; iww = 6; iwb = 7;
        iwr = 8; iow = 9; iob = 10; iei = 11; iet = 12; iidx = 13;
    }

    const float* x   = (const float*)d_in[ix];
    const int*   ei  = (const int*)d_in[iei];
    const int*   et  = (const int*)d_in[iet];
    const int*   idx = (const int*)d_in[iidx];
    const float* pw  = (const float*)d_in[ipw];
    const float* pb  = (const float*)d_in[ipb];
    const float* bg  = (const float*)d_in[ibg];
    const float* bb  = (const float*)d_in[ibb];
    const float* ww  = (const float*)d_in[iww];
    const float* wb  = (const float*)d_in[iwb];
    const float* wr  = (const float*)d_in[iwr];
    const float* ow  = (const float*)d_in[iow];
    const float* ob  = (const float*)d_in[iob];

    int E  = in_sizes[iei] / 2;
    int NI = out_size / 128;

    __half* xs  = (__half*)sym_addr(g_xs);
    __half* hs  = (__half*)sym_addr(g_hs);
    __half* zs  = (__half*)sym_addr(g_zs);
    float* bc0 = (float*)sym_addr(g_bc0);
    float* b01 = (float*)sym_addr(g_b01);
    __half* wc0h = (__half*)sym_addr(g_wc0h);
    __half* wc0l = (__half*)sym_addr(g_wc0l);
    __half* w01h = (__half*)sym_addr(g_w01h);
    __half* w01l = (__half*)sym_addr(g_w01l);
    __half* pwh = (__half*)sym_addr(g_pwh);
    __half* pwl = (__half*)sym_addr(g_pwl);
    __half* owh = (__half*)sym_addr(g_owh);
    __half* owl = (__half*)sym_addr(g_owl);

    // streams + events (host-side only, capture-legal)
    cudaStream_t s2, s3;
    cudaStreamCreateWithFlags(&s2, cudaStreamNonBlocking);
    cudaStreamCreateWithFlags(&s3, cudaStreamNonBlocking);
    cudaEvent_t evFork, evPrep1w, evJoin;
    cudaEventCreateWithFlags(&evFork, cudaEventDisableTiming);
    cudaEventCreateWithFlags(&evPrep1w, cudaEventDisableTiming);
    cudaEventCreateWithFlags(&evJoin, cudaEventDisableTiming);

    // fork
    cudaEventRecord(evFork, 0);
    cudaStreamWaitEvent(s2, evFork, 0);
    cudaStreamWaitEvent(s3, evFork, 0);

    // s2: CSR chain
    zero_kernel<<<(NN + 255) / 256, 256, 0, s2>>>();
    hist_kernel<<<(E + 255) / 256, 256, 0, s2>>>(ei, E);
    scan1_kernel<<<NB, 1024, 0, s2>>>();
    scan3_kernel<<<NB, 1024, 0, s2>>>(E);
    scatter_kernel<<<(E + 255) / 256, 256, 0, s2>>>(ei, et, E);

    // s3: weight prep (overlapped)
    prep1w_kernel<<<(181504 + 255) / 256, 256, 0, s3>>>(ow, ww, wr, wb);
    cudaEventRecord(evPrep1w, s3);

    // s2 tail: prep2 needs g_wc1 (prep1w) + after CSR
    cudaStreamWaitEvent(s2, evPrep1w, 0);
    prep2_kernel<<<(81920 + 640 + 255) / 256, 256, 0, s2>>>(ow, ob);
    cudaEventRecord(evJoin, s2);

    // main: critical-path prep (vectorized x conv + pw split) -> proj -> BN
    prep1x_kernel<<<(XS4 + 4096 + 255) / 256, 256>>>(x, pw);
    int mtiles = (NN + 127) / 128;
    gemm_f16<0><<<dim3(1, mtiles), 256>>>(xs, pwh, pwl, pb, nullptr, NN, 128, 128, nullptr);
    bnrelu_kernel<<<(NN * 32 + 255) / 256, 256>>>(bg, bb);

    // layer 0 GEMM needs wc0 (prep1w)
    cudaStreamWaitEvent(0, evPrep1w, 0);
    gemm_f16<1><<<dim3(5, mtiles), 256>>>(hs, wc0h, wc0l, bc0, nullptr, NN, 640, 0, nullptr);

    // join: edge stage needs CSR + prep2 (s2) + layer0 GEMM (main)
    cudaStreamWaitEvent(0, evJoin, 0);
    edge_kernel<<<(NN * 32 + 255) / 256, 256>>>();

    // layer 1 (fused layer0-out)
    gemm_f16<1><<<dim3(5, mtiles), 256>>>(zs, w01h, w01l, b01, nullptr, NN, 640, 0, nullptr);
    edge_kernel<<<(NN * 32 + 255) / 256, 256>>>();

    // final: out = gelu(z1[idx] @ out_w1 + ob1)
    gemm_f16<2><<<dim3(1, (NI + 127) / 128), 256>>>(zs, owh, owl, ob + 128, (float*)d_out,
                                                    NI, 128, 128, idx);

    cudaEventDestroy(evFork);
    cudaEventDestroy(evPrep1w);
    cudaEventDestroy(evJoin);
    cudaStreamDestroy(s2);
    cudaStreamDestroy(s3);
}